// round 2
// baseline (speedup 1.0000x reference)
#include <cuda_runtime.h>
#include <cuda_fp16.h>
#include <cstdint>

#define K_DIM 64
#define BM 128
#define BN 64
#define NTHREADS 256
#define LDAB 40   // uint (half2) row stride for A/B smem tiles
#define LDC 76    // float row stride for C staging tile
#define NB 55     // n-chunks per m-row -> grid = 8*55 = 440 blocks (one wave @3/SM)

__device__ float    g_partial[1024];
__device__ unsigned g_count = 0;

__device__ __forceinline__ int pgpos(int p) { return ((p & 3) << 1) | (p >> 2); }

__device__ __forceinline__ unsigned f2h2(float x, float y) {
    __half2 h = __floats2half2_rn(x, y);
    return *reinterpret_cast<unsigned*>(&h);
}

__global__ void __launch_bounds__(NTHREADS, 3)
mf_fused(const float* __restrict__ user_emb,
         const float* __restrict__ item_emb,
         const int*   __restrict__ uid,
         const int*   __restrict__ seq,
         float*       __restrict__ out,
         int N, int Bsz, int HIST, int ntiles)
{
    extern __shared__ unsigned smem[];
    unsigned* As = smem;                                   // BM x LDAB (half2)
    unsigned* Bs = smem + BM * LDAB;                       // BN x LDAB (half2)
    float*    Cs = (float*)(smem + (BM + BN) * LDAB);      // BM x LDC

    const int t    = threadIdx.x;
    const int lane = t & 31, wid = t >> 5;
    const int m0   = blockIdx.y * BM;
    const int nb   = gridDim.x;
    const int bid  = blockIdx.y * nb + blockIdx.x;
    const int nblocks = nb * gridDim.y;

    float lsum = 0.f;

    // ---- load A once: gather user rows, convert to half2, k-pair interleaved ----
    {
        int r  = t >> 1;
        int cb = (t & 1) * 32;
        int u  = uid[m0 + r];
        const float4* src = (const float4*)(user_emb + (size_t)u * K_DIM + cb);
        #pragma unroll
        for (int j = 0; j < 8; j++) {
            float4 v = src[j];
            int p0 = (cb + 4 * j) >> 1;
            As[r * LDAB + ((p0 >> 3) << 3) + pgpos(p0 & 7)]       = f2h2(v.x, v.y);
            As[r * LDAB + (((p0+1) >> 3) << 3) + pgpos((p0+1)&7)] = f2h2(v.z, v.w);
        }
    }

    // ---- B tile prefetch machinery (regs) ----
    float4 pv[4];
    const int br = t >> 2, bcb = (t & 3) * 16;
    auto loadB = [&](int tile) {
        int n0 = tile * BN;
        bool ok = (n0 + br) < N;
        const float4* src = (const float4*)(item_emb + (size_t)(n0 + br) * K_DIM + bcb);
        #pragma unroll
        for (int j = 0; j < 4; j++)
            pv[j] = ok ? src[j] : make_float4(0.f, 0.f, 0.f, 0.f);
    };
    auto storeB = [&]() {
        #pragma unroll
        for (int j = 0; j < 4; j++) {
            int p0 = (bcb + 4 * j) >> 1;
            Bs[br * LDAB + ((p0 >> 3) << 3) + pgpos(p0 & 7)]       = f2h2(pv[j].x, pv[j].y);
            Bs[br * LDAB + (((p0+1) >> 3) << 3) + pgpos((p0+1)&7)] = f2h2(pv[j].z, pv[j].w);
        }
    };

    loadB(blockIdx.x);
    __syncthreads();   // A ready

    const int g  = lane >> 2, tq = lane & 3;
    const int wm = (wid >> 1) * 32;
    const int wn = (wid & 1) * 32;
    const unsigned* Abase = As + (wm + g) * LDAB + 2 * tq;
    const unsigned* Bbase = Bs + (wn + g) * LDAB + 2 * tq;

    for (int tile = blockIdx.x; tile < ntiles; tile += nb) {
        storeB();
        __syncthreads();   // B ready; prev readback done
        int nxt = tile + nb;
        if (nxt < ntiles) loadB(nxt);

        float acc[2][4][4] = {};
        #pragma unroll
        for (int kk = 0; kk < 4; kk++) {
            unsigned a0[2], a1[2], a2[2], a3[2], b0[4], b1[4];
            #pragma unroll
            for (int mi = 0; mi < 2; mi++) {
                uint2 x = *(const uint2*)(Abase + (mi * 16)     * LDAB + kk * 8);
                uint2 y = *(const uint2*)(Abase + (mi * 16 + 8) * LDAB + kk * 8);
                a0[mi] = x.x; a2[mi] = x.y; a1[mi] = y.x; a3[mi] = y.y;
            }
            #pragma unroll
            for (int ni = 0; ni < 4; ni++) {
                uint2 z = *(const uint2*)(Bbase + (ni * 8) * LDAB + kk * 8);
                b0[ni] = z.x; b1[ni] = z.y;
            }
            #pragma unroll
            for (int mi = 0; mi < 2; mi++)
                #pragma unroll
                for (int ni = 0; ni < 4; ni++)
                    asm volatile(
                        "mma.sync.aligned.m16n8k16.row.col.f32.f16.f16.f32 "
                        "{%0,%1,%2,%3}, {%4,%5,%6,%7}, {%8,%9}, {%0,%1,%2,%3};\n"
                        : "+f"(acc[mi][ni][0]), "+f"(acc[mi][ni][1]),
                          "+f"(acc[mi][ni][2]), "+f"(acc[mi][ni][3])
                        : "r"(a0[mi]), "r"(a1[mi]), "r"(a2[mi]), "r"(a3[mi]),
                          "r"(b0[ni]), "r"(b1[ni]));
        }

        // stage accumulators -> smem C (STS.64 pairs)
        #pragma unroll
        for (int mi = 0; mi < 2; mi++) {
            int r0 = wm + mi * 16 + g;
            #pragma unroll
            for (int ni = 0; ni < 4; ni++) {
                int c = wn + ni * 8 + 2 * tq;
                *(float2*)&Cs[r0 * LDC + c]       = make_float2(acc[mi][ni][0], acc[mi][ni][1]);
                *(float2*)&Cs[(r0 + 8) * LDC + c] = make_float2(acc[mi][ni][2], acc[mi][ni][3]);
            }
        }
        __syncthreads();   // C complete; B fully consumed

        // readback C rows, vector-store to gmem (out+1 misalignment handled)
        {
            int row = t & 127, h = t >> 7;
            int n0 = tile * BN;
            int nrem = min(BN, N - n0);
            const float* Crow = Cs + row * LDC + h * 32;
            float w[32];
            #pragma unroll
            for (int j = 0; j < 8; j++)
                *(float4*)&w[4 * j] = *(const float4*)(Crow + 4 * j);
            float* gp = out + 1 + (size_t)(m0 + row) * N + n0;
            if (nrem == BN) {
                if (h == 0) {
                    gp[0] = w[0];
                    *(float2*)&gp[1] = make_float2(w[1], w[2]);
                    #pragma unroll
                    for (int k2 = 0; k2 < 7; k2++)
                        *(float4*)&gp[3 + 4 * k2] =
                            make_float4(w[3+4*k2], w[4+4*k2], w[5+4*k2], w[6+4*k2]);
                } else {
                    float wex = Cs[row * LDC + 31];
                    *(float4*)&gp[31] = make_float4(wex, w[0], w[1], w[2]);
                    #pragma unroll
                    for (int k2 = 1; k2 < 8; k2++)
                        *(float4*)&gp[31 + 4 * k2] =
                            make_float4(w[4*k2-1], w[4*k2], w[4*k2+1], w[4*k2+2]);
                    gp[63] = w[31];
                }
            } else {
                int ce = min(h * 32 + 32, nrem);
                for (int c = h * 32; c < ce; c++) gp[c] = w[c - h * 32];
            }
            #pragma unroll
            for (int j = 0; j < 32; j++) lsum += w[j] * w[j];  // OOB cols are exact zeros
        }
        // no sync needed: next storeB touches B only; sync after storeB joins stragglers
    }

    // ---- positives: distinct (row, seq[row,h]) -> 1 - 2*dot, spread over all warps ----
    {
        int TW    = nblocks * (NTHREADS / 32);
        int Wg    = bid * (NTHREADS / 32) + wid;
        int total = Bsz * HIST;
        int chunk = (total + TW - 1) / TW;
        int pbeg = Wg * chunk, pend = min(pbeg + chunk, total);
        int cur_r = -1, s0 = -1, s1 = -1;
        float2 uv = make_float2(0.f, 0.f);
        float pl = 0.f;
        for (int p = pbeg; p < pend; p++) {
            int r = p / HIST, h = p % HIST;
            if (r != cur_r) {
                cur_r = r;
                s0 = (lane < HIST)      ? seq[r * HIST + lane]      : -1;
                s1 = (lane + 32 < HIST) ? seq[r * HIST + lane + 32] : -1;
                int u = uid[r];
                uv = *(const float2*)(user_emb + (size_t)u * K_DIM + 2 * lane);
            }
            int sh = (h < 32) ? __shfl_sync(0xffffffffu, s0, h)
                              : __shfl_sync(0xffffffffu, s1, h - 32);
            unsigned d0 = __ballot_sync(0xffffffffu, lane < h && s0 == sh);
            unsigned d1 = __ballot_sync(0xffffffffu, (lane + 32) < h && s1 == sh);
            if ((d0 | d1) == 0) {   // first occurrence
                float2 iv = *(const float2*)(item_emb + (size_t)sh * K_DIM + 2 * lane);
                float d = uv.x * iv.x + uv.y * iv.y;
                #pragma unroll
                for (int o = 16; o; o >>= 1) d += __shfl_xor_sync(0xffffffffu, d, o);
                pl += 1.0f - 2.0f * d;
            }
        }
        if (lane == 0) lsum += pl;
    }

    // ---- block reduce -> g_partial; last block folds everything into out[0] ----
    #pragma unroll
    for (int o = 16; o; o >>= 1) lsum += __shfl_xor_sync(0xffffffffu, lsum, o);
    __shared__ float wls[NTHREADS / 32];
    __shared__ int lastflag;
    if (lane == 0) wls[wid] = lsum;
    __syncthreads();
    if (t == 0) {
        float s = 0.f;
        #pragma unroll
        for (int i = 0; i < NTHREADS / 32; i++) s += wls[i];
        g_partial[bid] = s;
        __threadfence();
        unsigned tk = atomicAdd(&g_count, 1u);
        lastflag = (tk == (unsigned)(nblocks - 1));
    }
    __syncthreads();
    if (lastflag) {
        __threadfence();
        volatile float* gpart = g_partial;
        float s = 0.f;
        for (int i = t; i < nblocks; i += NTHREADS) s += gpart[i];
        #pragma unroll
        for (int o = 16; o; o >>= 1) s += __shfl_xor_sync(0xffffffffu, s, o);
        if (lane == 0) wls[wid] = s;
        __syncthreads();
        if (t == 0) {
            float tot = 0.f;
            #pragma unroll
            for (int i = 0; i < NTHREADS / 32; i++) tot += wls[i];
            out[0] = tot;
            g_count = 0;   // reset for next graph replay
        }
    }
}

extern "C" void kernel_launch(void* const* d_in, const int* in_sizes, int n_in,
                              void* d_out, int out_size) {
    const float* user_emb = (const float*)d_in[0];
    const float* item_emb = (const float*)d_in[1];
    const int*   uid      = (const int*)d_in[2];
    const int*   seq      = (const int*)d_in[3];
    float* out = (float*)d_out;

    int Bsz    = in_sizes[2];
    int N      = in_sizes[1] / K_DIM;
    int HIST   = in_sizes[3] / Bsz;
    int ntiles = (N + BN - 1) / BN;
    int mtiles = Bsz / BM;

    size_t smem_bytes = (size_t)((BM + BN) * LDAB + BM * LDC) * 4;
    cudaFuncSetAttribute(mf_fused, cudaFuncAttributeMaxDynamicSharedMemorySize,
                         (int)smem_bytes);

    dim3 grid(NB, mtiles);
    mf_fused<<<grid, NTHREADS, smem_bytes>>>(user_emb, item_emb, uid, seq, out,
                                             N, Bsz, HIST, ntiles);
}

// round 5
// speedup vs baseline: 1.9871x; 1.9871x over previous
#include <cuda_runtime.h>
#include <cuda_fp16.h>
#include <cstdint>

#define K_DIM 64
#define BM 128
#define BN 64
#define NTHREADS 256
#define LDAB 40   // uint (half2) row stride for A/B smem tiles
#define LDC 76    // float row stride for C staging tile
#define NB 37     // n-chunks per m-row -> grid = 8*37 = 296 = 2 blocks/SM, one wave

__device__ float    g_partial[1024];
__device__ unsigned g_count = 0;

__device__ __forceinline__ int pgpos(int p) { return ((p & 3) << 1) | (p >> 2); }

__device__ __forceinline__ unsigned f2h2(float x, float y) {
    __half2 h = __floats2half2_rn(x, y);
    return *reinterpret_cast<unsigned*>(&h);
}

__global__ void __launch_bounds__(NTHREADS, 2)
mf_fused(const float* __restrict__ user_emb,
         const float* __restrict__ item_emb,
         const int*   __restrict__ uid,
         const int*   __restrict__ seq,
         float*       __restrict__ out,
         int N, int Bsz, int HIST, int ntiles)
{
    extern __shared__ unsigned smem[];
    unsigned* As = smem;                                   // BM x LDAB (half2)
    unsigned* Bs = smem + BM * LDAB;                       // BN x LDAB (half2)
    float*    Cs = (float*)(smem + (BM + BN) * LDAB);      // BM x LDC

    const int t    = threadIdx.x;
    const int lane = t & 31, wid = t >> 5;
    const int m0   = blockIdx.y * BM;
    const int nb   = gridDim.x;
    const int bid  = blockIdx.y * nb + blockIdx.x;
    const int nblocks = nb * gridDim.y;

    float lsum = 0.f;

    // ---- load A once: gather user rows, convert to half2, k-pair interleaved ----
    {
        int r  = t >> 1;
        int cb = (t & 1) * 32;
        int u  = uid[m0 + r];
        const float4* src = (const float4*)(user_emb + (size_t)u * K_DIM + cb);
        #pragma unroll
        for (int j = 0; j < 8; j++) {
            float4 v = src[j];
            int p0 = (cb + 4 * j) >> 1;
            As[r * LDAB + ((p0 >> 3) << 3) + pgpos(p0 & 7)]       = f2h2(v.x, v.y);
            As[r * LDAB + (((p0+1) >> 3) << 3) + pgpos((p0+1)&7)] = f2h2(v.z, v.w);
        }
    }

    // ---- B tile prefetch machinery (regs) ----
    float4 pv[4];
    const int br = t >> 2, bcb = (t & 3) * 16;
    auto loadB = [&](int tile) {
        int n0 = tile * BN;
        bool ok = (n0 + br) < N;
        const float4* src = (const float4*)(item_emb + (size_t)(n0 + br) * K_DIM + bcb);
        #pragma unroll
        for (int j = 0; j < 4; j++)
            pv[j] = ok ? src[j] : make_float4(0.f, 0.f, 0.f, 0.f);
    };
    auto storeB = [&]() {
        #pragma unroll
        for (int j = 0; j < 4; j++) {
            int p0 = (bcb + 4 * j) >> 1;
            Bs[br * LDAB + ((p0 >> 3) << 3) + pgpos(p0 & 7)]       = f2h2(pv[j].x, pv[j].y);
            Bs[br * LDAB + (((p0+1) >> 3) << 3) + pgpos((p0+1)&7)] = f2h2(pv[j].z, pv[j].w);
        }
    };

    loadB(blockIdx.x);
    __syncthreads();   // A ready

    const int g  = lane >> 2, tq = lane & 3;
    const int wm = (wid >> 1) * 32;
    const int wn = (wid & 1) * 32;
    const unsigned* Abase = As + (wm + g) * LDAB + 2 * tq;
    const unsigned* Bbase = Bs + (wn + g) * LDAB + 2 * tq;

    // ---- hoist A fragments into registers (block-invariant across tiles) ----
    unsigned af[2][4][4];   // [mi][kk][a0..a3]
    #pragma unroll
    for (int kk = 0; kk < 4; kk++)
        #pragma unroll
        for (int mi = 0; mi < 2; mi++) {
            uint2 x = *(const uint2*)(Abase + (mi * 16)     * LDAB + kk * 8);
            uint2 y = *(const uint2*)(Abase + (mi * 16 + 8) * LDAB + kk * 8);
            af[mi][kk][0] = x.x; af[mi][kk][2] = x.y;
            af[mi][kk][1] = y.x; af[mi][kk][3] = y.y;
        }

    const int l16  = lane & 15;
    const int rsel = lane >> 4;

    for (int tile = blockIdx.x; tile < ntiles; tile += nb) {
        storeB();
        __syncthreads();   // B ready; prev readback done
        int nxt = tile + nb;
        if (nxt < ntiles) loadB(nxt);

        float acc[2][4][4] = {};
        #pragma unroll
        for (int kk = 0; kk < 4; kk++) {
            unsigned b0[4], b1[4];
            #pragma unroll
            for (int ni = 0; ni < 4; ni++) {
                uint2 z = *(const uint2*)(Bbase + (ni * 8) * LDAB + kk * 8);
                b0[ni] = z.x; b1[ni] = z.y;
            }
            #pragma unroll
            for (int mi = 0; mi < 2; mi++)
                #pragma unroll
                for (int ni = 0; ni < 4; ni++)
                    asm volatile(
                        "mma.sync.aligned.m16n8k16.row.col.f32.f16.f16.f32 "
                        "{%0,%1,%2,%3}, {%4,%5,%6,%7}, {%8,%9}, {%0,%1,%2,%3};\n"
                        : "+f"(acc[mi][ni][0]), "+f"(acc[mi][ni][1]),
                          "+f"(acc[mi][ni][2]), "+f"(acc[mi][ni][3])
                        : "r"(af[mi][kk][0]), "r"(af[mi][kk][1]),
                          "r"(af[mi][kk][2]), "r"(af[mi][kk][3]),
                          "r"(b0[ni]), "r"(b1[ni]));
        }

        // stage accumulators -> smem C (aligned STS.64 pairs)
        #pragma unroll
        for (int mi = 0; mi < 2; mi++) {
            int r0 = wm + mi * 16 + g;
            #pragma unroll
            for (int ni = 0; ni < 4; ni++) {
                int c = wn + ni * 8 + 2 * tq;
                *(float2*)&Cs[r0 * LDC + c]       = make_float2(acc[mi][ni][0], acc[mi][ni][1]);
                *(float2*)&Cs[(r0 + 8) * LDC + c] = make_float2(acc[mi][ni][2], acc[mi][ni][3]);
            }
        }
        __syncthreads();   // C complete; B fully consumed

        // coalesced readback: half-warp covers one full row (64 cols).
        // smem read is ALIGNED (4*l16); realignment to the gmem col==3 (mod 4)
        // 16B boundary is done with shfl_down by 1 lane.
        {
            int n0 = tile * BN;
            int nrem = min(BN, N - n0);
            if (nrem == BN) {
                #pragma unroll
                for (int pass = 0; pass < 8; pass++) {
                    int row = pass * 16 + wid * 2 + rsel;
                    const float* Crow = Cs + row * LDC;
                    float* gp = out + 1 + (size_t)(m0 + row) * N + n0;
                    float4 v = *(const float4*)(Crow + 4 * l16);   // aligned LDS.128
                    float nx = __shfl_down_sync(0xffffffffu, v.x, 1);
                    float ny = __shfl_down_sync(0xffffffffu, v.y, 1);
                    float nz = __shfl_down_sync(0xffffffffu, v.z, 1);
                    if (l16 < 15)
                        __stcs((float4*)(gp + 3 + 4 * l16),
                               make_float4(v.w, nx, ny, nz));      // aligned STG.128
                    if (l16 == 0) {
                        __stcs(gp, v.x);
                        __stcs((float2*)(gp + 1), make_float2(v.y, v.z));
                    }
                    if (l16 == 15)
                        __stcs(gp + 63, v.w);
                    lsum += v.x*v.x + v.y*v.y + v.z*v.z + v.w*v.w; // each col once
                }
            } else {
                #pragma unroll
                for (int pass = 0; pass < 8; pass++) {
                    int row = pass * 16 + wid * 2 + rsel;
                    const float* Crow = Cs + row * LDC;
                    float* gp = out + 1 + (size_t)(m0 + row) * N + n0;
                    for (int c = l16; c < nrem; c += 16) {
                        float v = Crow[c];
                        __stcs(gp + c, v);
                        lsum += v * v;
                    }
                }
            }
        }
        // no sync needed: storeB (next iter) writes Bs only; the sync after
        // storeB joins stragglers before anyone touches Cs again.
    }

    // ---- positives: distinct (row, seq[row,h]) -> 1 - 2*dot, spread over all warps ----
    {
        int TW    = nblocks * (NTHREADS / 32);
        int Wg    = bid * (NTHREADS / 32) + wid;
        int total = Bsz * HIST;
        int chunk = (total + TW - 1) / TW;
        int pbeg = Wg * chunk, pend = min(pbeg + chunk, total);
        int cur_r = -1, s0 = -1, s1 = -1;
        float2 uv = make_float2(0.f, 0.f);
        float pl = 0.f;
        for (int p = pbeg; p < pend; p++) {
            int r = p / HIST, h = p % HIST;
            if (r != cur_r) {
                cur_r = r;
                s0 = (lane < HIST)      ? seq[r * HIST + lane]      : -1;
                s1 = (lane + 32 < HIST) ? seq[r * HIST + lane + 32] : -1;
                int u = uid[r];
                uv = *(const float2*)(user_emb + (size_t)u * K_DIM + 2 * lane);
            }
            int sh = (h < 32) ? __shfl_sync(0xffffffffu, s0, h)
                              : __shfl_sync(0xffffffffu, s1, h - 32);
            unsigned d0 = __ballot_sync(0xffffffffu, lane < h && s0 == sh);
            unsigned d1 = __ballot_sync(0xffffffffu, (lane + 32) < h && s1 == sh);
            if ((d0 | d1) == 0) {   // first occurrence
                float2 iv = *(const float2*)(item_emb + (size_t)sh * K_DIM + 2 * lane);
                float d = uv.x * iv.x + uv.y * iv.y;
                #pragma unroll
                for (int o = 16; o; o >>= 1) d += __shfl_xor_sync(0xffffffffu, d, o);
                pl += 1.0f - 2.0f * d;
            }
        }
        if (lane == 0) lsum += pl;
    }

    // ---- block reduce -> g_partial; last block folds everything into out[0] ----
    #pragma unroll
    for (int o = 16; o; o >>= 1) lsum += __shfl_xor_sync(0xffffffffu, lsum, o);
    __shared__ float wls[NTHREADS / 32];
    __shared__ int lastflag;
    if (lane == 0) wls[wid] = lsum;
    __syncthreads();
    if (t == 0) {
        float s = 0.f;
        #pragma unroll
        for (int i = 0; i < NTHREADS / 32; i++) s += wls[i];
        g_partial[bid] = s;
        __threadfence();
        unsigned tk = atomicAdd(&g_count, 1u);
        lastflag = (tk == (unsigned)(nblocks - 1));
    }
    __syncthreads();
    if (lastflag) {
        __threadfence();
        volatile float* gpart = g_partial;
        float s = 0.f;
        for (int i = t; i < nblocks; i += NTHREADS) s += gpart[i];
        #pragma unroll
        for (int o = 16; o; o >>= 1) s += __shfl_xor_sync(0xffffffffu, s, o);
        if (lane == 0) wls[wid] = s;
        __syncthreads();
        if (t == 0) {
            float tot = 0.f;
            #pragma unroll
            for (int i = 0; i < NTHREADS / 32; i++) tot += wls[i];
            out[0] = tot;
            g_count = 0;   // reset for next graph replay
        }
    }
}

extern "C" void kernel_launch(void* const* d_in, const int* in_sizes, int n_in,
                              void* d_out, int out_size) {
    const float* user_emb = (const float*)d_in[0];
    const float* item_emb = (const float*)d_in[1];
    const int*   uid      = (const int*)d_in[2];
    const int*   seq      = (const int*)d_in[3];
    float* out = (float*)d_out;

    int Bsz    = in_sizes[2];
    int N      = in_sizes[1] / K_DIM;
    int HIST   = in_sizes[3] / Bsz;
    int ntiles = (N + BN - 1) / BN;
    int mtiles = Bsz / BM;

    size_t smem_bytes = (size_t)((BM + BN) * LDAB + BM * LDC) * 4;
    cudaFuncSetAttribute(mf_fused, cudaFuncAttributeMaxDynamicSharedMemorySize,
                         (int)smem_bytes);

    dim3 grid(NB, mtiles);
    mf_fused<<<grid, NTHREADS, smem_bytes>>>(user_emb, item_emb, uid, seq, out,
                                             N, Bsz, HIST, ntiles);
}

// round 6
// speedup vs baseline: 2.9992x; 1.5093x over previous
#include <cuda_runtime.h>
#include <cuda_fp16.h>
#include <cstdint>

#define K_DIM 64
#define BM 128
#define BN 64
#define NTHREADS 256
#define LDAB 40   // uint (half2) row stride for A/B smem tiles
#define NB 37     // grid = 8*37 = 296 = 2 blocks/SM, one wave
#define MAX_ITEMS 100352

__device__ __half    g_item_half[(size_t)MAX_ITEMS * K_DIM];  // interleaved k-pairs
__device__ float     g_partial[1024];
__device__ unsigned  g_count = 0;

__device__ __forceinline__ int pgpos(int p) { return ((p & 3) << 1) | (p >> 2); }

__device__ __forceinline__ unsigned f2h2(float x, float y) {
    __half2 h = __floats2half2_rn(x, y);
    return *reinterpret_cast<unsigned*>(&h);
}

__device__ __forceinline__ float2 sel2(bool c, float2 a, float2 b) {
    return make_float2(c ? a.x : b.x, c ? a.y : b.y);
}

// Pre-convert item_emb fp32 -> half, k-pair interleaved per row (matches the
// mma fragment layout so loadB is a straight uint4 copy).
__global__ void cvt_kernel(const float* __restrict__ item, int N) {
    int i = blockIdx.x * blockDim.x + threadIdx.x;
    if (i >= N * 4) return;
    int r = i >> 2, s = i & 3;   // row, 16-float group
    const float4* src = (const float4*)(item + (size_t)r * K_DIM + s * 16);
    float4 f0 = src[0], f1 = src[1], f2 = src[2], f3 = src[3];
    unsigned u[8];
    u[0] = f2h2(f0.x, f0.y);  // pair 0 -> pos 0
    u[2] = f2h2(f0.z, f0.w);  // pair 1 -> pos 2
    u[4] = f2h2(f1.x, f1.y);  // pair 2 -> pos 4
    u[6] = f2h2(f1.z, f1.w);  // pair 3 -> pos 6
    u[1] = f2h2(f2.x, f2.y);  // pair 4 -> pos 1
    u[3] = f2h2(f2.z, f2.w);  // pair 5 -> pos 3
    u[5] = f2h2(f3.x, f3.y);  // pair 6 -> pos 5
    u[7] = f2h2(f3.z, f3.w);  // pair 7 -> pos 7
    uint4* dst = (uint4*)(g_item_half + (size_t)r * K_DIM + s * 16);
    dst[0] = make_uint4(u[0], u[1], u[2], u[3]);
    dst[1] = make_uint4(u[4], u[5], u[6], u[7]);
}

__global__ void __launch_bounds__(NTHREADS, 2)
mf_fused(const float* __restrict__ user_emb,
         const float* __restrict__ item_emb,
         const int*   __restrict__ uid,
         const int*   __restrict__ seq,
         float*       __restrict__ out,
         int N, int Bsz, int HIST, int ntiles)
{
    extern __shared__ unsigned smem[];
    unsigned* As = smem;                 // BM x LDAB (half2)
    unsigned* Bs = smem + BM * LDAB;     // BN x LDAB (half2)

    const int t    = threadIdx.x;
    const int lane = t & 31, wid = t >> 5;
    const int m0   = blockIdx.y * BM;
    const int nb   = gridDim.x;
    const int bid  = blockIdx.y * nb + blockIdx.x;
    const int nblocks = nb * gridDim.y;

    float lsum = 0.f;

    // ---- load A once: gather user rows, convert to half2, k-pair interleaved ----
    {
        int r  = t >> 1;
        int cb = (t & 1) * 32;
        int u  = uid[m0 + r];
        const float4* src = (const float4*)(user_emb + (size_t)u * K_DIM + cb);
        #pragma unroll
        for (int j = 0; j < 8; j++) {
            float4 v = src[j];
            int p0 = (cb + 4 * j) >> 1;
            As[r * LDAB + ((p0 >> 3) << 3) + pgpos(p0 & 7)]       = f2h2(v.x, v.y);
            As[r * LDAB + (((p0+1) >> 3) << 3) + pgpos((p0+1)&7)] = f2h2(v.z, v.w);
        }
    }

    // ---- B prefetch: uint4 copies from pre-interleaved half array ----
    // lane mapping: i = t + it*256, row = i>>3, q8 = i&7  (dense LDG + conflict-free STS.128)
    uint4 pv[2];
    auto loadB = [&](int n0, int ncols) {
        #pragma unroll
        for (int it = 0; it < 2; it++) {
            int i = t + it * NTHREADS;
            int row = i >> 3, q8 = i & 7;
            if (row < ncols)
                pv[it] = *((const uint4*)(g_item_half + (size_t)(n0 + row) * K_DIM) + q8);
            else
                pv[it] = make_uint4(0u, 0u, 0u, 0u);
        }
    };
    auto storeB = [&]() {
        #pragma unroll
        for (int it = 0; it < 2; it++) {
            int i = t + it * NTHREADS;
            int row = i >> 3, q8 = i & 7;
            *(uint4*)(Bs + row * LDAB + q8 * 4) = pv[it];
        }
    };
    auto win_n0    = [&](int tile) { return tile == 0 ? 0 : tile * 64 - 1; };
    auto win_ncols = [&](int tile) {
        int n0 = win_n0(tile);
        int w  = tile == 0 ? 63 : 64;
        return min(w, N - n0);
    };

    loadB(win_n0(blockIdx.x), win_ncols(blockIdx.x));
    __syncthreads();   // A ready

    const int g  = lane >> 2, tq = lane & 3;
    const int wm = (wid >> 1) * 32;
    const int wn = (wid & 1) * 32;
    const unsigned* Abase = As + (wm + g) * LDAB + 2 * tq;
    const unsigned* Bbase = Bs + (wn + g) * LDAB + 2 * tq;

    // ---- hoist A fragments into registers (block-invariant across tiles) ----
    unsigned af[2][4][4];
    #pragma unroll
    for (int kk = 0; kk < 4; kk++)
        #pragma unroll
        for (int mi = 0; mi < 2; mi++) {
            uint2 x = *(const uint2*)(Abase + (mi * 16)     * LDAB + kk * 8);
            uint2 y = *(const uint2*)(Abase + (mi * 16 + 8) * LDAB + kk * 8);
            af[mi][kk][0] = x.x; af[mi][kk][2] = x.y;
            af[mi][kk][1] = y.x; af[mi][kk][3] = y.y;
        }

    const bool qb = tq & 1;
    const bool qc = tq & 2;

    for (int tile = blockIdx.x; tile < ntiles; tile += nb) {
        const int n0    = win_n0(tile);
        const int ncols = win_ncols(tile);
        const bool full = (tile > 0) && (n0 + 64 <= N);

        storeB();
        __syncthreads();   // B ready (also guards prior tile's reads)
        int nxt = tile + nb;
        if (nxt < ntiles) loadB(win_n0(nxt), win_ncols(nxt));

        float acc[2][4][4] = {};
        #pragma unroll
        for (int kk = 0; kk < 4; kk++) {
            unsigned b0[4], b1[4];
            #pragma unroll
            for (int ni = 0; ni < 4; ni++) {
                uint2 z = *(const uint2*)(Bbase + (ni * 8) * LDAB + kk * 8);
                b0[ni] = z.x; b1[ni] = z.y;
            }
            #pragma unroll
            for (int mi = 0; mi < 2; mi++)
                #pragma unroll
                for (int ni = 0; ni < 4; ni++)
                    asm volatile(
                        "mma.sync.aligned.m16n8k16.row.col.f32.f16.f16.f32 "
                        "{%0,%1,%2,%3}, {%4,%5,%6,%7}, {%8,%9}, {%0,%1,%2,%3};\n"
                        : "+f"(acc[mi][ni][0]), "+f"(acc[mi][ni][1]),
                          "+f"(acc[mi][ni][2]), "+f"(acc[mi][ni][3])
                        : "r"(af[mi][kk][0]), "r"(af[mi][kk][1]),
                          "r"(af[mi][kk][2]), "r"(af[mi][kk][3]),
                          "r"(b0[ni]), "r"(b1[ni]));
        }
        __syncthreads();   // all Bs reads done; epilogue overlaps next storeB

        // ---- epilogue: 4x4 quad shuffle-transpose -> thread owns 8 contiguous cols ----
        #pragma unroll
        for (int mi = 0; mi < 2; mi++)
            #pragma unroll
            for (int h = 0; h < 2; h++) {
                float2 v0 = make_float2(acc[mi][0][2*h], acc[mi][0][2*h+1]);
                float2 v1 = make_float2(acc[mi][1][2*h], acc[mi][1][2*h+1]);
                float2 v2 = make_float2(acc[mi][2][2*h], acc[mi][2][2*h+1]);
                float2 v3 = make_float2(acc[mi][3][2*h], acc[mi][3][2*h+1]);
                // round 1 (xor 1): exchange slots {!b, !b+2}
                float2 ta = sel2(qb, v0, v1);
                float2 tb = sel2(qb, v2, v3);
                ta.x = __shfl_xor_sync(0xffffffffu, ta.x, 1);
                ta.y = __shfl_xor_sync(0xffffffffu, ta.y, 1);
                tb.x = __shfl_xor_sync(0xffffffffu, tb.x, 1);
                tb.y = __shfl_xor_sync(0xffffffffu, tb.y, 1);
                v0 = sel2(qb, ta, v0);  v1 = sel2(qb, v1, ta);
                v2 = sel2(qb, tb, v2);  v3 = sel2(qb, v3, tb);
                // round 2 (xor 2): exchange slots {2-2c, 3-2c}
                float2 tc = sel2(qc, v0, v2);
                float2 td = sel2(qc, v1, v3);
                tc.x = __shfl_xor_sync(0xffffffffu, tc.x, 2);
                tc.y = __shfl_xor_sync(0xffffffffu, tc.y, 2);
                td.x = __shfl_xor_sync(0xffffffffu, td.x, 2);
                td.y = __shfl_xor_sync(0xffffffffu, td.y, 2);
                v0 = sel2(qc, tc, v0);  v2 = sel2(qc, v2, tc);
                v1 = sel2(qc, td, v1);  v3 = sel2(qc, v3, td);
                // thread now holds cols wn + 8*tq + 0..7 of row below
                int row = m0 + wm + mi * 16 + h * 8 + g;
                float* gp = out + 1 + (size_t)row * N + n0 + wn + 8 * tq;
                if (full) {
                    __stcs((float4*)gp,       make_float4(v0.x, v0.y, v1.x, v1.y));
                    __stcs((float4*)(gp + 4), make_float4(v2.x, v2.y, v3.x, v3.y));
                } else {
                    int lc = wn + 8 * tq;
                    if (lc + 0 < ncols) __stcs(gp + 0, v0.x);
                    if (lc + 1 < ncols) __stcs(gp + 1, v0.y);
                    if (lc + 2 < ncols) __stcs(gp + 2, v1.x);
                    if (lc + 3 < ncols) __stcs(gp + 3, v1.y);
                    if (lc + 4 < ncols) __stcs(gp + 4, v2.x);
                    if (lc + 5 < ncols) __stcs(gp + 5, v2.y);
                    if (lc + 6 < ncols) __stcs(gp + 6, v3.x);
                    if (lc + 7 < ncols) __stcs(gp + 7, v3.y);
                }
                // padded cols are exact zeros -> safe to always accumulate
                lsum += v0.x*v0.x + v0.y*v0.y + v1.x*v1.x + v1.y*v1.y
                      + v2.x*v2.x + v2.y*v2.y + v3.x*v3.x + v3.y*v3.y;
            }
    }

    // ---- positives: distinct (row, seq[row,h]) -> 1 - 2*dot, spread over all warps ----
    {
        int TW    = nblocks * (NTHREADS / 32);
        int Wg    = bid * (NTHREADS / 32) + wid;
        int total = Bsz * HIST;
        int chunk = (total + TW - 1) / TW;
        int pbeg = Wg * chunk, pend = min(pbeg + chunk, total);
        int cur_r = -1, s0 = -1, s1 = -1;
        float2 uv = make_float2(0.f, 0.f);
        float pl = 0.f;
        for (int p = pbeg; p < pend; p++) {
            int r = p / HIST, h = p % HIST;
            if (r != cur_r) {
                cur_r = r;
                s0 = (lane < HIST)      ? seq[r * HIST + lane]      : -1;
                s1 = (lane + 32 < HIST) ? seq[r * HIST + lane + 32] : -1;
                int u = uid[r];
                uv = *(const float2*)(user_emb + (size_t)u * K_DIM + 2 * lane);
            }
            int sh = (h < 32) ? __shfl_sync(0xffffffffu, s0, h)
                              : __shfl_sync(0xffffffffu, s1, h - 32);
            unsigned d0 = __ballot_sync(0xffffffffu, lane < h && s0 == sh);
            unsigned d1 = __ballot_sync(0xffffffffu, (lane + 32) < h && s1 == sh);
            if ((d0 | d1) == 0) {   // first occurrence
                float2 iv = *(const float2*)(item_emb + (size_t)sh * K_DIM + 2 * lane);
                float d = uv.x * iv.x + uv.y * iv.y;
                #pragma unroll
                for (int o = 16; o; o >>= 1) d += __shfl_xor_sync(0xffffffffu, d, o);
                pl += 1.0f - 2.0f * d;
            }
        }
        if (lane == 0) lsum += pl;
    }

    // ---- block reduce -> g_partial; last block folds everything into out[0] ----
    #pragma unroll
    for (int o = 16; o; o >>= 1) lsum += __shfl_xor_sync(0xffffffffu, lsum, o);
    __shared__ float wls[NTHREADS / 32];
    __shared__ int lastflag;
    if (lane == 0) wls[wid] = lsum;
    __syncthreads();
    if (t == 0) {
        float s = 0.f;
        #pragma unroll
        for (int i = 0; i < NTHREADS / 32; i++) s += wls[i];
        g_partial[bid] = s;
        __threadfence();
        unsigned tk = atomicAdd(&g_count, 1u);
        lastflag = (tk == (unsigned)(nblocks - 1));
    }
    __syncthreads();
    if (lastflag) {
        __threadfence();
        volatile float* gpart = g_partial;
        float s = 0.f;
        for (int i = t; i < nblocks; i += NTHREADS) s += gpart[i];
        #pragma unroll
        for (int o = 16; o; o >>= 1) s += __shfl_xor_sync(0xffffffffu, s, o);
        if (lane == 0) wls[wid] = s;
        __syncthreads();
        if (t == 0) {
            float tot = 0.f;
            #pragma unroll
            for (int i = 0; i < NTHREADS / 32; i++) tot += wls[i];
            out[0] = tot;
            g_count = 0;   // reset for next graph replay
        }
    }
}

extern "C" void kernel_launch(void* const* d_in, const int* in_sizes, int n_in,
                              void* d_out, int out_size) {
    const float* user_emb = (const float*)d_in[0];
    const float* item_emb = (const float*)d_in[1];
    const int*   uid      = (const int*)d_in[2];
    const int*   seq      = (const int*)d_in[3];
    float* out = (float*)d_out;

    int Bsz    = in_sizes[2];
    int N      = in_sizes[1] / K_DIM;
    int HIST   = in_sizes[3] / Bsz;
    // aligned windows: tile0 = 63 cols, tile t>=1 = [64t-1, 64t+63)
    int ntiles = (N <= 63) ? 1 : (1 + N / 64);
    int mtiles = Bsz / BM;

    size_t smem_bytes = (size_t)((BM + BN) * LDAB) * 4;
    cudaFuncSetAttribute(mf_fused, cudaFuncAttributeMaxDynamicSharedMemorySize,
                         (int)smem_bytes);

    cvt_kernel<<<(N * 4 + 255) / 256, 256>>>(item_emb, N);

    dim3 grid(NB, mtiles);
    mf_fused<<<grid, NTHREADS, smem_bytes>>>(user_emb, item_emb, uid, seq, out,
                                             N, Bsz, HIST, ntiles);
}

// round 8
// speedup vs baseline: 3.2360x; 1.0790x over previous
#include <cuda_runtime.h>
#include <cuda_fp16.h>
#include <cstdint>

#define K_DIM 64
#define BM 128
#define BN 64
#define NTHREADS 256
#define LDAB 40   // uint (half2) row stride for A/B smem tiles
#define NB 37     // grid = 8*37 = 296 = 2 blocks/SM, one wave
#define MAX_ITEMS 100352

__device__ __half    g_item_half[(size_t)MAX_ITEMS * K_DIM];  // interleaved k-pairs
__device__ float     g_partial[1024];
__device__ unsigned  g_count = 0;

__device__ __forceinline__ int pgpos(int p) { return ((p & 3) << 1) | (p >> 2); }

__device__ __forceinline__ unsigned f2h2(float x, float y) {
    __half2 h = __floats2half2_rn(x, y);
    return *reinterpret_cast<unsigned*>(&h);
}

__device__ __forceinline__ float2 sel2(bool c, float2 a, float2 b) {
    return make_float2(c ? a.x : b.x, c ? a.y : b.y);
}

// Pre-convert item_emb fp32 -> half, k-pair interleaved per row (matches the
// mma fragment layout so the B fill is a straight 16B copy).
__global__ void cvt_kernel(const float* __restrict__ item, int N) {
    int i = blockIdx.x * blockDim.x + threadIdx.x;
    if (i >= N * 4) return;
    int r = i >> 2, s = i & 3;   // row, 16-float group
    const float4* src = (const float4*)(item + (size_t)r * K_DIM + s * 16);
    float4 f0 = src[0], f1 = src[1], f2 = src[2], f3 = src[3];
    unsigned u[8];
    u[0] = f2h2(f0.x, f0.y);
    u[2] = f2h2(f0.z, f0.w);
    u[4] = f2h2(f1.x, f1.y);
    u[6] = f2h2(f1.z, f1.w);
    u[1] = f2h2(f2.x, f2.y);
    u[3] = f2h2(f2.z, f2.w);
    u[5] = f2h2(f3.x, f3.y);
    u[7] = f2h2(f3.z, f3.w);
    uint4* dst = (uint4*)(g_item_half + (size_t)r * K_DIM + s * 16);
    dst[0] = make_uint4(u[0], u[1], u[2], u[3]);
    dst[1] = make_uint4(u[4], u[5], u[6], u[7]);
}

__global__ void __launch_bounds__(NTHREADS, 2)
mf_fused(const float* __restrict__ user_emb,
         const float* __restrict__ item_emb,
         const int*   __restrict__ uid,
         const int*   __restrict__ seq,
         float*       __restrict__ out,
         int N, int Bsz, int HIST, int ntiles)
{
    extern __shared__ unsigned smem[];
    unsigned* As = smem;                               // BM x LDAB (half2)
    unsigned* Bsb[2] = { smem + BM * LDAB,
                         smem + BM * LDAB + BN * LDAB };

    const int t    = threadIdx.x;
    const int lane = t & 31, wid = t >> 5;
    const int m0   = blockIdx.y * BM;
    const int nb   = gridDim.x;
    const int bid  = blockIdx.y * nb + blockIdx.x;
    const int nblocks = nb * gridDim.y;

    float lsum = 0.f;

    // ---- load A once: gather user rows, convert to half2, k-pair interleaved ----
    {
        int r  = t >> 1;
        int cb = (t & 1) * 32;
        int u  = uid[m0 + r];
        const float4* src = (const float4*)(user_emb + (size_t)u * K_DIM + cb);
        #pragma unroll
        for (int j = 0; j < 8; j++) {
            float4 v = src[j];
            int p0 = (cb + 4 * j) >> 1;
            As[r * LDAB + ((p0 >> 3) << 3) + pgpos(p0 & 7)]       = f2h2(v.x, v.y);
            As[r * LDAB + (((p0+1) >> 3) << 3) + pgpos((p0+1)&7)] = f2h2(v.z, v.w);
        }
    }

    auto win_n0    = [&](int tile) { return tile == 0 ? 0 : tile * 64 - 1; };
    auto win_ncols = [&](int tile) {
        int n0 = win_n0(tile);
        int w  = tile == 0 ? 63 : 64;
        return min(w, N - n0);
    };

    const unsigned bsaddr0 = (unsigned)__cvta_generic_to_shared(Bsb[0]);
    const unsigned bsaddr1 = (unsigned)__cvta_generic_to_shared(Bsb[1]);

    // cp.async B fill: 16B per thread x2, zero-fill rows past ncols
    auto issueB = [&](int tile, int buf) {
        int n0 = win_n0(tile), ncols = win_ncols(tile);
        unsigned base = buf ? bsaddr1 : bsaddr0;
        #pragma unroll
        for (int it = 0; it < 2; it++) {
            int i = t + it * NTHREADS;
            int row = i >> 3, q8 = i & 7;
            const void* src = (const uint4*)(g_item_half + (size_t)(n0 + row) * K_DIM) + q8;
            unsigned dst = base + (unsigned)(row * LDAB + q8 * 4) * 4u;
            int sz = (row < ncols) ? 16 : 0;
            asm volatile("cp.async.cg.shared.global [%0], [%1], 16, %2;"
                         :: "r"(dst), "l"(src), "r"(sz) : "memory");
        }
        asm volatile("cp.async.commit_group;" ::: "memory");
    };

    issueB(blockIdx.x, 0);
    __syncthreads();   // A ready

    const int g  = lane >> 2, tq = lane & 3;
    const int wm = (wid >> 1) * 32;
    const int wn = (wid & 1) * 32;
    const unsigned* Abase = As + (wm + g) * LDAB + 2 * tq;

    // ---- hoist A fragments into registers (block-invariant across tiles) ----
    unsigned af[2][4][4];
    #pragma unroll
    for (int kk = 0; kk < 4; kk++)
        #pragma unroll
        for (int mi = 0; mi < 2; mi++) {
            uint2 x = *(const uint2*)(Abase + (mi * 16)     * LDAB + kk * 8);
            uint2 y = *(const uint2*)(Abase + (mi * 16 + 8) * LDAB + kk * 8);
            af[mi][kk][0] = x.x; af[mi][kk][2] = x.y;
            af[mi][kk][1] = y.x; af[mi][kk][3] = y.y;
        }

    const bool qb = tq & 1;
    const bool qc = tq & 2;
    const bool lo = g < 4;
    int pb = 0;

    for (int tile = blockIdx.x; tile < ntiles; tile += nb) {
        const int n0    = win_n0(tile);
        const int ncols = win_ncols(tile);
        const bool full = (tile > 0) && (n0 + 64 <= N);

        asm volatile("cp.async.wait_group 0;" ::: "memory");
        __syncthreads();   // Bs[pb] filled & visible; prior reads of Bs[pb^1] done
        int nxt = tile + nb;
        if (nxt < ntiles) issueB(nxt, pb ^ 1);

        const unsigned* Bbase = Bsb[pb] + (wn + g) * LDAB + 2 * tq;

        float acc[2][4][4] = {};
        #pragma unroll
        for (int kk = 0; kk < 4; kk++) {
            unsigned b0[4], b1[4];
            #pragma unroll
            for (int ni = 0; ni < 4; ni++) {
                uint2 z = *(const uint2*)(Bbase + (ni * 8) * LDAB + kk * 8);
                b0[ni] = z.x; b1[ni] = z.y;
            }
            #pragma unroll
            for (int mi = 0; mi < 2; mi++)
                #pragma unroll
                for (int ni = 0; ni < 4; ni++)
                    asm volatile(
                        "mma.sync.aligned.m16n8k16.row.col.f32.f16.f16.f32 "
                        "{%0,%1,%2,%3}, {%4,%5,%6,%7}, {%8,%9}, {%0,%1,%2,%3};\n"
                        : "+f"(acc[mi][ni][0]), "+f"(acc[mi][ni][1]),
                          "+f"(acc[mi][ni][2]), "+f"(acc[mi][ni][3])
                        : "r"(af[mi][kk][0]), "r"(af[mi][kk][1]),
                          "r"(af[mi][kk][2]), "r"(af[mi][kk][3]),
                          "r"(b0[ni]), "r"(b1[ni]));
        }

        // ---- epilogue: quad transpose -> thread owns 8 contiguous cols;
        //      xor-16 half-chunk exchange -> each STG.128 = 4 FULL 128B lines ----
        #pragma unroll
        for (int mi = 0; mi < 2; mi++)
            #pragma unroll
            for (int h = 0; h < 2; h++) {
                float2 v0 = make_float2(acc[mi][0][2*h], acc[mi][0][2*h+1]);
                float2 v1 = make_float2(acc[mi][1][2*h], acc[mi][1][2*h+1]);
                float2 v2 = make_float2(acc[mi][2][2*h], acc[mi][2][2*h+1]);
                float2 v3 = make_float2(acc[mi][3][2*h], acc[mi][3][2*h+1]);
                // round 1 (xor 1)
                float2 ta = sel2(qb, v0, v1);
                float2 tb = sel2(qb, v2, v3);
                ta.x = __shfl_xor_sync(0xffffffffu, ta.x, 1);
                ta.y = __shfl_xor_sync(0xffffffffu, ta.y, 1);
                tb.x = __shfl_xor_sync(0xffffffffu, tb.x, 1);
                tb.y = __shfl_xor_sync(0xffffffffu, tb.y, 1);
                v0 = sel2(qb, ta, v0);  v1 = sel2(qb, v1, ta);
                v2 = sel2(qb, tb, v2);  v3 = sel2(qb, v3, tb);
                // round 2 (xor 2)
                float2 tc = sel2(qc, v0, v2);
                float2 td = sel2(qc, v1, v3);
                tc.x = __shfl_xor_sync(0xffffffffu, tc.x, 2);
                tc.y = __shfl_xor_sync(0xffffffffu, tc.y, 2);
                td.x = __shfl_xor_sync(0xffffffffu, td.x, 2);
                td.y = __shfl_xor_sync(0xffffffffu, td.y, 2);
                v0 = sel2(qc, tc, v0);  v2 = sel2(qc, v2, tc);
                v1 = sel2(qc, td, v1);  v3 = sel2(qc, v3, td);
                // thread (g,tq): row r0+g, cols wn+8tq..+7
                lsum += v0.x*v0.x + v0.y*v0.y + v1.x*v1.x + v1.y*v1.y
                      + v2.x*v2.x + v2.y*v2.y + v3.x*v3.x + v3.y*v3.y;
                int r0 = m0 + wm + mi * 16 + h * 8;
                if (full) {
                    // xor-16 exchange: g<4 sends chunkH (v2,v3), g>=4 sends chunkL (v0,v1)
                    float s0 = lo ? v2.x : v0.x;
                    float s1 = lo ? v2.y : v0.y;
                    float s2 = lo ? v3.x : v1.x;
                    float s3 = lo ? v3.y : v1.y;
                    float w0 = __shfl_xor_sync(0xffffffffu, s0, 16);
                    float w1 = __shfl_xor_sync(0xffffffffu, s1, 16);
                    float w2 = __shfl_xor_sync(0xffffffffu, s2, 16);
                    float w3 = __shfl_xor_sync(0xffffffffu, s3, 16);
                    float4 valA = lo ? make_float4(v0.x, v0.y, v1.x, v1.y)
                                     : make_float4(w0, w1, w2, w3);
                    float4 valB = lo ? make_float4(w0, w1, w2, w3)
                                     : make_float4(v2.x, v2.y, v3.x, v3.y);
                    int rA = r0 + (g & 3);
                    size_t cidx = (size_t)1 + n0 + wn + 8 * tq + (lo ? 0 : 4);
                    float* gpA = out + cidx + (size_t)rA * N;
                    float* gpB = out + cidx + (size_t)(rA + 4) * N;
                    __stcs((float4*)gpA, valA);   // rows r0..r0+3: full lines
                    __stcs((float4*)gpB, valB);   // rows r0+4..r0+7
                } else {
                    int lc = wn + 8 * tq;
                    float* gp = out + 1 + (size_t)(r0 + g) * N + n0 + lc;
                    if (lc + 0 < ncols) __stcs(gp + 0, v0.x);
                    if (lc + 1 < ncols) __stcs(gp + 1, v0.y);
                    if (lc + 2 < ncols) __stcs(gp + 2, v1.x);
                    if (lc + 3 < ncols) __stcs(gp + 3, v1.y);
                    if (lc + 4 < ncols) __stcs(gp + 4, v2.x);
                    if (lc + 5 < ncols) __stcs(gp + 5, v2.y);
                    if (lc + 6 < ncols) __stcs(gp + 6, v3.x);
                    if (lc + 7 < ncols) __stcs(gp + 7, v3.y);
                }
            }
        pb ^= 1;
    }

    // ---- positives: distinct (row, seq[row,h]) -> 1 - 2*dot, spread over all warps ----
    {
        int TW    = nblocks * (NTHREADS / 32);
        int Wg    = bid * (NTHREADS / 32) + wid;
        int total = Bsz * HIST;
        int chunk = (total + TW - 1) / TW;
        int pbeg = Wg * chunk, pend = min(pbeg + chunk, total);
        int cur_r = -1, s0 = -1, s1 = -1;
        float2 uv = make_float2(0.f, 0.f);
        float pl = 0.f;
        for (int p = pbeg; p < pend; p++) {
            int r = p / HIST, h = p % HIST;
            if (r != cur_r) {
                cur_r = r;
                s0 = (lane < HIST)      ? seq[r * HIST + lane]      : -1;
                s1 = (lane + 32 < HIST) ? seq[r * HIST + lane + 32] : -1;
                int u = uid[r];
                uv = *(const float2*)(user_emb + (size_t)u * K_DIM + 2 * lane);
            }
            int sh = (h < 32) ? __shfl_sync(0xffffffffu, s0, h)
                              : __shfl_sync(0xffffffffu, s1, h - 32);
            unsigned d0 = __ballot_sync(0xffffffffu, lane < h && s0 == sh);
            unsigned d1 = __ballot_sync(0xffffffffu, (lane + 32) < h && s1 == sh);
            if ((d0 | d1) == 0) {   // first occurrence
                float2 iv = *(const float2*)(item_emb + (size_t)sh * K_DIM + 2 * lane);
                float d = uv.x * iv.x + uv.y * iv.y;
                #pragma unroll
                for (int o = 16; o; o >>= 1) d += __shfl_xor_sync(0xffffffffu, d, o);
                pl += 1.0f - 2.0f * d;
            }
        }
        if (lane == 0) lsum += pl;
    }

    // ---- block reduce -> g_partial; last block folds everything into out[0] ----
    #pragma unroll
    for (int o = 16; o; o >>= 1) lsum += __shfl_xor_sync(0xffffffffu, lsum, o);
    __shared__ float wls[NTHREADS / 32];
    __shared__ int lastflag;
    if (lane == 0) wls[wid] = lsum;
    __syncthreads();
    if (t == 0) {
        float s = 0.f;
        #pragma unroll
        for (int i = 0; i < NTHREADS / 32; i++) s += wls[i];
        g_partial[bid] = s;
        __threadfence();
        unsigned tk = atomicAdd(&g_count, 1u);
        lastflag = (tk == (unsigned)(nblocks - 1));
    }
    __syncthreads();
    if (lastflag) {
        __threadfence();
        volatile float* gpart = g_partial;
        float s = 0.f;
        for (int i = t; i < nblocks; i += NTHREADS) s += gpart[i];
        #pragma unroll
        for (int o = 16; o; o >>= 1) s += __shfl_xor_sync(0xffffffffu, s, o);
        if (lane == 0) wls[wid] = s;
        __syncthreads();
        if (t == 0) {
            float tot = 0.f;
            #pragma unroll
            for (int i = 0; i < NTHREADS / 32; i++) tot += wls[i];
            out[0] = tot;
            g_count = 0;   // reset for next graph replay
        }
    }
}

extern "C" void kernel_launch(void* const* d_in, const int* in_sizes, int n_in,
                              void* d_out, int out_size) {
    const float* user_emb = (const float*)d_in[0];
    const float* item_emb = (const float*)d_in[1];
    const int*   uid      = (const int*)d_in[2];
    const int*   seq      = (const int*)d_in[3];
    float* out = (float*)d_out;

    int Bsz    = in_sizes[2];
    int N      = in_sizes[1] / K_DIM;
    int HIST   = in_sizes[3] / Bsz;
    // aligned windows: tile0 = 63 cols, tile t>=1 = [64t-1, 64t+63)
    int ntiles = (N <= 63) ? 1 : (1 + N / 64);
    int mtiles = Bsz / BM;

    size_t smem_bytes = (size_t)((BM + 2 * BN) * LDAB) * 4;
    cudaFuncSetAttribute(mf_fused, cudaFuncAttributeMaxDynamicSharedMemorySize,
                         (int)smem_bytes);

    cvt_kernel<<<(N * 4 + 255) / 256, 256>>>(item_emb, N);

    dim3 grid(NB, mtiles);
    mf_fused<<<grid, NTHREADS, smem_bytes>>>(user_emb, item_emb, uid, seq, out,
                                             N, Bsz, HIST, ntiles);
}